// round 4
// baseline (speedup 1.0000x reference)
#include <cuda_runtime.h>
#include <cstdint>

#define N_NODES  50000
#define N_EDGES  800000
#define N_GRAPHS 512
#define D_H      64
#define E_DIM    16
#define SCAN_BS  256
#define N_SCAN_BLOCKS ((N_NODES + SCAN_BS - 1) / SCAN_BS)   // 196

// ---------------------------------------------------------------------------
// Static scratch (no dynamic allocation allowed).
__device__ __align__(16) float g_h[N_NODES * D_H];       // node features
__device__ __align__(16) float g_z[N_NODES * D_H];       // z = h + aggr
__device__ float g_s[N_NODES];                           // last-layer per-node scalar
__device__ float g_pooled[N_GRAPHS];                     // per-graph mean
__device__ int   g_gcnt[N_GRAPHS];                       // nodes per graph
__device__ int   g_gptr[N_GRAPHS + 1];                   // graph -> node range (batch sorted)
__device__ int   g_cnt[N_NODES];                         // in-degree histogram
__device__ int   g_sloc[N_NODES];                        // block-local inclusive scans
__device__ int   g_bsum[N_SCAN_BLOCKS];                  // per-block sums
__device__ int   g_rowptr[N_NODES + 1];
__device__ int   g_cursor[N_NODES];
__device__ int   g_elist[N_EDGES];                       // edge ids grouped by dst
__device__ int   g_src32[N_EDGES];

// ---------------------------------------------------------------------------
__global__ void kzero_small() {
    int t = blockIdx.x * blockDim.x + threadIdx.x;
    if (t < N_GRAPHS) g_gcnt[t] = 0;
    for (int i = t; i < N_NODES; i += gridDim.x * blockDim.x) g_cnt[i] = 0;
}

// graph-size histogram (int atomics) + copy x -> g_h
__global__ void kprep_nodes(const int* __restrict__ batch,
                            const float4* __restrict__ x) {
    int i = blockIdx.x * blockDim.x + threadIdx.x;
    int stride = gridDim.x * blockDim.x;
    if (i < N_NODES) atomicAdd(&g_gcnt[batch[i]], 1);
    float4* h4 = reinterpret_cast<float4*>(g_h);
    const int n4 = N_NODES * D_H / 4;
    for (int j = i; j < n4; j += stride) h4[j] = x[j];
}

// copy src column + in-degree histogram (edge_index is int32: [2, N_EDGES])
__global__ void kprep_edges(const int* __restrict__ ei) {
    int e = blockIdx.x * blockDim.x + threadIdx.x;
    if (e >= N_EDGES) return;
    g_src32[e] = ei[e];
    atomicAdd(&g_cnt[ei[N_EDGES + e]], 1);
}

// inclusive scan of g_gcnt (512 elems, 1 block) -> g_gptr
__global__ void kscan_g() {
    __shared__ int sh[N_GRAPHS];
    const int t = threadIdx.x;
    int v = g_gcnt[t];
    sh[t] = v;
    __syncthreads();
    for (int off = 1; off < N_GRAPHS; off <<= 1) {
        int add = (t >= off) ? sh[t - off] : 0;
        __syncthreads();
        sh[t] += add;
        __syncthreads();
    }
    g_gptr[t + 1] = sh[t];
    if (t == 0) g_gptr[0] = 0;
}

// ---- 3-kernel exclusive scan over g_cnt (50000 elems) ----
__global__ void kscan1() {
    __shared__ int sh[SCAN_BS];
    const int t = threadIdx.x;
    const int i = blockIdx.x * SCAN_BS + t;
    int v = (i < N_NODES) ? g_cnt[i] : 0;
    sh[t] = v;
    __syncthreads();
    for (int off = 1; off < SCAN_BS; off <<= 1) {
        int add = (t >= off) ? sh[t - off] : 0;
        __syncthreads();
        sh[t] += add;
        __syncthreads();
    }
    if (i < N_NODES) g_sloc[i] = sh[t];
    if (t == SCAN_BS - 1) g_bsum[blockIdx.x] = sh[t];
}

__global__ void kscan2() {
    __shared__ int sh[SCAN_BS];
    const int t = threadIdx.x;
    int v = (t < N_SCAN_BLOCKS) ? g_bsum[t] : 0;
    sh[t] = v;
    __syncthreads();
    for (int off = 1; off < SCAN_BS; off <<= 1) {
        int add = (t >= off) ? sh[t - off] : 0;
        __syncthreads();
        sh[t] += add;
        __syncthreads();
    }
    if (t < N_SCAN_BLOCKS) g_bsum[t] = sh[t] - v;   // exclusive
}

__global__ void kscan3() {
    int i = blockIdx.x * blockDim.x + threadIdx.x;
    if (i < N_NODES) {
        int ex = g_sloc[i] - g_cnt[i] + g_bsum[i / SCAN_BS];
        g_rowptr[i] = ex;
        g_cursor[i] = ex;
        if (i == 0) g_rowptr[N_NODES] = N_EDGES;
    }
}

__global__ void kfill(const int* __restrict__ ei) {
    int e = blockIdx.x * blockDim.x + threadIdx.x;
    if (e >= N_EDGES) return;
    int pos = atomicAdd(&g_cursor[ei[N_EDGES + e]], 1);
    g_elist[pos] = e;
}

// ---------------------------------------------------------------------------
// Aggregation (gather form, no atomics): one warp per dst node.
// Lane owns output channels (2*lane, 2*lane+1); We column slice in registers.
// g_z[dst] = g_h[dst] + sum_{in-edges} relu(g_h[src] + We.edge_attr + be).
__global__ void kaggr(const float* __restrict__ ea,
                      const float* __restrict__ We,
                      const float* __restrict__ be,
                      int layer) {
    const int lane = threadIdx.x & 31;
    const int dst = (blockIdx.x * blockDim.x + threadIdx.x) >> 5;
    if (dst >= N_NODES) return;

    const float* W = We + layer * E_DIM * D_H;
    float2 Wr[E_DIM];
    #pragma unroll
    for (int j = 0; j < E_DIM; j++)
        Wr[j] = *reinterpret_cast<const float2*>(W + j * D_H + 2 * lane);
    const float2 bias = *reinterpret_cast<const float2*>(be + layer * D_H + 2 * lane);

    const int kb = g_rowptr[dst];
    const int ke = g_rowptr[dst + 1];

    float2 acc = make_float2(0.f, 0.f);
    int eid = (kb < ke) ? g_elist[kb] : 0;
    for (int k = kb; k < ke; k++) {
        const int src = g_src32[eid];
        const float4* a4 = reinterpret_cast<const float4*>(ea + (long)eid * E_DIM);
        float a[E_DIM];
        reinterpret_cast<float4*>(a)[0] = a4[0];
        reinterpret_cast<float4*>(a)[1] = a4[1];
        reinterpret_cast<float4*>(a)[2] = a4[2];
        reinterpret_cast<float4*>(a)[3] = a4[3];
        eid = (k + 1 < ke) ? g_elist[k + 1] : 0;   // prefetch next edge id

        float2 p = bias;
        #pragma unroll
        for (int j = 0; j < E_DIM; j++) {
            p.x += a[j] * Wr[j].x;
            p.y += a[j] * Wr[j].y;
        }
        const float2 hv = *reinterpret_cast<const float2*>(g_h + (long)src * D_H + 2 * lane);
        acc.x += fmaxf(hv.x + p.x, 0.f);
        acc.y += fmaxf(hv.y + p.y, 0.f);
    }

    const float2 hd = *reinterpret_cast<const float2*>(g_h + (long)dst * D_H + 2 * lane);
    float2 z;
    z.x = hd.x + acc.x;
    z.y = hd.y + acc.y;
    *reinterpret_cast<float2*>(g_z + (long)dst * D_H + 2 * lane) = z;
}

// ---------------------------------------------------------------------------
// Node kernel (layers 0..2): h = relu(z @ W_l + b_l). Warp per node.
__global__ void knode(const float* __restrict__ W_hidden,
                      const float* __restrict__ b_hidden,
                      int layer) {
    __shared__ float Ws[D_H * D_H];  // 16 KB
    __shared__ float bsh[D_H];
    const float* W = W_hidden + layer * D_H * D_H;
    for (int i = threadIdx.x; i < D_H * D_H / 4; i += blockDim.x)
        reinterpret_cast<float4*>(Ws)[i] = reinterpret_cast<const float4*>(W)[i];
    for (int i = threadIdx.x; i < D_H; i += blockDim.x)
        bsh[i] = (b_hidden + layer * D_H)[i];
    __syncthreads();

    const int lane = threadIdx.x & 31;
    const int gw = (blockIdx.x * blockDim.x + threadIdx.x) >> 5;
    const int nw = (gridDim.x * blockDim.x) >> 5;
    const float2* Ws2 = reinterpret_cast<const float2*>(Ws);

    for (int i = gw; i < N_NODES; i += nw) {
        float acc0 = bsh[2 * lane];
        float acc1 = bsh[2 * lane + 1];
        const float4* z4 = reinterpret_cast<const float4*>(g_z + (long)i * D_H);
        #pragma unroll
        for (int jj = 0; jj < 16; jj++) {
            const float4 zv = z4[jj];
            const int j = jj * 4;
            float2 w;
            w = Ws2[(j + 0) * 32 + lane]; acc0 += zv.x * w.x; acc1 += zv.x * w.y;
            w = Ws2[(j + 1) * 32 + lane]; acc0 += zv.y * w.x; acc1 += zv.y * w.y;
            w = Ws2[(j + 2) * 32 + lane]; acc0 += zv.z * w.x; acc1 += zv.z * w.y;
            w = Ws2[(j + 3) * 32 + lane]; acc0 += zv.w * w.x; acc1 += zv.w * w.y;
        }
        float2 r;
        r.x = fmaxf(acc0, 0.f);
        r.y = fmaxf(acc1, 0.f);
        reinterpret_cast<float2*>(g_h + (long)i * D_H)[lane] = r;
    }
}

// ---------------------------------------------------------------------------
// Final layer: g_s[i] = z_i . W_out + b_out  (plain store, no atomics)
__global__ void knode3(const float* __restrict__ W_out,
                       const float* __restrict__ b_out) {
    __shared__ float Ws[D_H];
    for (int i = threadIdx.x; i < D_H; i += blockDim.x) Ws[i] = W_out[i];
    __syncthreads();

    const int lane = threadIdx.x & 31;
    const int gw = (blockIdx.x * blockDim.x + threadIdx.x) >> 5;
    const int nw = (gridDim.x * blockDim.x) >> 5;
    const float b0 = b_out[0];

    for (int i = gw; i < N_NODES; i += nw) {
        const float u0 = g_z[(long)i * D_H + lane];
        const float u1 = g_z[(long)i * D_H + 32 + lane];
        float acc = u0 * Ws[lane] + u1 * Ws[32 + lane];
        #pragma unroll
        for (int o = 16; o > 0; o >>= 1)
            acc += __shfl_xor_sync(0xffffffffu, acc, o);
        if (lane == 0) g_s[i] = acc + b0;
    }
}

// ---------------------------------------------------------------------------
// Segmented mean pool: warp per graph (batch sorted -> contiguous node ranges)
__global__ void kpool() {
    const int lane = threadIdx.x & 31;
    const int g = (blockIdx.x * blockDim.x + threadIdx.x) >> 5;
    if (g >= N_GRAPHS) return;
    const int s0 = g_gptr[g];
    const int s1 = g_gptr[g + 1];
    float acc = 0.f;
    for (int i = s0 + lane; i < s1; i += 32) acc += g_s[i];
    #pragma unroll
    for (int o = 16; o > 0; o >>= 1)
        acc += __shfl_xor_sync(0xffffffffu, acc, o);
    if (lane == 0) g_pooled[g] = acc / fmaxf((float)(s1 - s0), 1.0f);
}

// ---------------------------------------------------------------------------
// batchnorm (training stats, biased var) -> sigmoid
__global__ void kfinal(const float* __restrict__ gamma,
                       const float* __restrict__ beta,
                       float* __restrict__ out) {
    __shared__ float sh[N_GRAPHS];
    const int t = threadIdx.x;
    const float p = g_pooled[t];

    sh[t] = p;
    __syncthreads();
    for (int s = N_GRAPHS / 2; s > 0; s >>= 1) {
        if (t < s) sh[t] += sh[t + s];
        __syncthreads();
    }
    const float m = sh[0] / (float)N_GRAPHS;
    __syncthreads();

    const float d = p - m;
    sh[t] = d * d;
    __syncthreads();
    for (int s = N_GRAPHS / 2; s > 0; s >>= 1) {
        if (t < s) sh[t] += sh[t + s];
        __syncthreads();
    }
    const float v = sh[0] / (float)N_GRAPHS;

    const float y = gamma[0] * d * rsqrtf(v + 1e-5f) + beta[0];
    out[t] = 1.0f / (1.0f + expf(-y));
}

// ---------------------------------------------------------------------------
extern "C" void kernel_launch(void* const* d_in, const int* in_sizes, int n_in,
                              void* d_out, int out_size) {
    const float* x    = (const float*)d_in[0];
    const int*   ei   = (const int*)d_in[1];     // int32! (JAX x64 disabled)
    const float* ea   = (const float*)d_in[2];
    const int*   bat  = (const int*)d_in[3];     // int32!
    const float* Wh   = (const float*)d_in[4];
    const float* bh   = (const float*)d_in[5];
    const float* We   = (const float*)d_in[6];
    const float* be   = (const float*)d_in[7];
    const float* Wout = (const float*)d_in[8];
    const float* bout = (const float*)d_in[9];
    const float* gam  = (const float*)d_in[10];
    const float* bet  = (const float*)d_in[11];
    float* out = (float*)d_out;

    // --- prep + CSR build ---
    kzero_small<<<64, 256>>>();
    kprep_nodes<<<(N_NODES + 255) / 256, 256>>>(bat, (const float4*)x);
    kprep_edges<<<(N_EDGES + 255) / 256, 256>>>(ei);
    kscan_g<<<1, N_GRAPHS>>>();
    kscan1<<<N_SCAN_BLOCKS, SCAN_BS>>>();
    kscan2<<<1, SCAN_BS>>>();
    kscan3<<<(N_NODES + 255) / 256, 256>>>();
    kfill<<<(N_EDGES + 255) / 256, 256>>>(ei);

    // --- 4 GINE layers ---
    const int aggr_blocks = (N_NODES * 32 + 255) / 256;  // warp per node
    for (int l = 0; l < 4; l++) {
        kaggr<<<aggr_blocks, 256>>>(ea, We, be, l);
        if (l < 3) knode<<<592, 256>>>(Wh, bh, l);
        else       knode3<<<592, 256>>>(Wout, bout);
    }

    kpool<<<(N_GRAPHS * 32 + 255) / 256, 256>>>();
    kfinal<<<1, N_GRAPHS>>>(gam, bet, out);
}

// round 5
// speedup vs baseline: 1.1382x; 1.1382x over previous
#include <cuda_runtime.h>
#include <cstdint>

#define N_NODES  50000
#define N_EDGES  800000
#define N_GRAPHS 512
#define D_H      64
#define E_DIM    16
#define SCAN_BS  256
#define N_SCAN_BLOCKS ((N_NODES + SCAN_BS - 1) / SCAN_BS)   // 196

// ---------------------------------------------------------------------------
// Static scratch (no dynamic allocation allowed).
__device__ __align__(16) float g_hA[N_NODES * D_H];
__device__ __align__(16) float g_hB[N_NODES * D_H];
__device__ __align__(16) float g_ea_perm[N_EDGES * E_DIM];   // 51.2 MB, dst-ordered
__device__ int   g_src_perm[N_EDGES];                        // dst-ordered src
__device__ float g_s[N_NODES];                               // last-layer scalar
__device__ float g_pooled[N_GRAPHS];
__device__ int   g_cnt[N_NODES];
__device__ int   g_sloc[N_NODES];
__device__ int   g_bsum[N_SCAN_BLOCKS];
__device__ int   g_rowptr[N_NODES + 1];
__device__ int   g_cursor[N_NODES];

// ---------------------------------------------------------------------------
__global__ void kzero_cnt() {
    int t = blockIdx.x * blockDim.x + threadIdx.x;
    for (int i = t; i < N_NODES; i += gridDim.x * blockDim.x) g_cnt[i] = 0;
}

// in-degree histogram (edge_index int32: [2, N_EDGES])
__global__ void kprep_edges(const int* __restrict__ ei) {
    int e = blockIdx.x * blockDim.x + threadIdx.x;
    if (e < N_EDGES) atomicAdd(&g_cnt[ei[N_EDGES + e]], 1);
}

// ---- 3-kernel exclusive scan over g_cnt ----
__global__ void kscan1() {
    __shared__ int sh[SCAN_BS];
    const int t = threadIdx.x;
    const int i = blockIdx.x * SCAN_BS + t;
    int v = (i < N_NODES) ? g_cnt[i] : 0;
    sh[t] = v;
    __syncthreads();
    for (int off = 1; off < SCAN_BS; off <<= 1) {
        int add = (t >= off) ? sh[t - off] : 0;
        __syncthreads();
        sh[t] += add;
        __syncthreads();
    }
    if (i < N_NODES) g_sloc[i] = sh[t];
    if (t == SCAN_BS - 1) g_bsum[blockIdx.x] = sh[t];
}

__global__ void kscan2() {
    __shared__ int sh[SCAN_BS];
    const int t = threadIdx.x;
    int v = (t < N_SCAN_BLOCKS) ? g_bsum[t] : 0;
    sh[t] = v;
    __syncthreads();
    for (int off = 1; off < SCAN_BS; off <<= 1) {
        int add = (t >= off) ? sh[t - off] : 0;
        __syncthreads();
        sh[t] += add;
        __syncthreads();
    }
    if (t < N_SCAN_BLOCKS) g_bsum[t] = sh[t] - v;   // exclusive
}

__global__ void kscan3() {
    int i = blockIdx.x * blockDim.x + threadIdx.x;
    if (i < N_NODES) {
        int ex = g_sloc[i] - g_cnt[i] + g_bsum[i / SCAN_BS];
        g_rowptr[i] = ex;
        g_cursor[i] = ex;
        if (i == 0) g_rowptr[N_NODES] = N_EDGES;
    }
}

// scatter edges into dst-order, copying src id AND the 64B edge_attr row.
__global__ void kfillperm(const int* __restrict__ ei,
                          const float4* __restrict__ ea4) {
    int e = blockIdx.x * blockDim.x + threadIdx.x;
    if (e >= N_EDGES) return;
    int pos = atomicAdd(&g_cursor[ei[N_EDGES + e]], 1);
    g_src_perm[pos] = ei[e];
    float4* dst = reinterpret_cast<float4*>(g_ea_perm) + (size_t)pos * 4;
    const float4* src = ea4 + (size_t)e * 4;
    dst[0] = src[0];
    dst[1] = src[1];
    dst[2] = src[2];
    dst[3] = src[3];
}

// ---------------------------------------------------------------------------
// Edge accumulation core: warp per dst node; lane owns channels (2l, 2l+1).
// Returns acc = sum over in-edges of relu(hin[src] + We.ea + be) + hin[dst].
__device__ __forceinline__ float2 edge_accum(const float* __restrict__ hin,
                                             const float2* __restrict__ Wr,  // [E_DIM]
                                             float2 bias, int dst, int lane) {
    const int kb = g_rowptr[dst];
    const int ke = g_rowptr[dst + 1];
    float2 acc = make_float2(0.f, 0.f);

    int k = kb;
    for (; k + 2 <= ke; k += 2) {
        const int s0 = g_src_perm[k];
        const int s1 = g_src_perm[k + 1];
        // issue both dependent gathers first
        const float2 h0 = *reinterpret_cast<const float2*>(hin + (size_t)s0 * D_H + 2 * lane);
        const float2 h1 = *reinterpret_cast<const float2*>(hin + (size_t)s1 * D_H + 2 * lane);

        float2 p0 = bias, p1 = bias;
        const float4* A0 = reinterpret_cast<const float4*>(g_ea_perm + (size_t)k * E_DIM);
        #pragma unroll
        for (int c = 0; c < 4; c++) {
            const float4 a0 = A0[c];
            const float4 a1 = A0[4 + c];
            const float2 w0 = Wr[4 * c + 0], w1 = Wr[4 * c + 1];
            const float2 w2 = Wr[4 * c + 2], w3 = Wr[4 * c + 3];
            p0.x += a0.x * w0.x + a0.y * w1.x + a0.z * w2.x + a0.w * w3.x;
            p0.y += a0.x * w0.y + a0.y * w1.y + a0.z * w2.y + a0.w * w3.y;
            p1.x += a1.x * w0.x + a1.y * w1.x + a1.z * w2.x + a1.w * w3.x;
            p1.y += a1.x * w0.y + a1.y * w1.y + a1.z * w2.y + a1.w * w3.y;
        }
        acc.x += fmaxf(h0.x + p0.x, 0.f) + fmaxf(h1.x + p1.x, 0.f);
        acc.y += fmaxf(h0.y + p0.y, 0.f) + fmaxf(h1.y + p1.y, 0.f);
    }
    if (k < ke) {
        const int s0 = g_src_perm[k];
        const float2 h0 = *reinterpret_cast<const float2*>(hin + (size_t)s0 * D_H + 2 * lane);
        float2 p0 = bias;
        const float4* A0 = reinterpret_cast<const float4*>(g_ea_perm + (size_t)k * E_DIM);
        #pragma unroll
        for (int c = 0; c < 4; c++) {
            const float4 a0 = A0[c];
            p0.x += a0.x * Wr[4*c].x + a0.y * Wr[4*c+1].x + a0.z * Wr[4*c+2].x + a0.w * Wr[4*c+3].x;
            p0.y += a0.x * Wr[4*c].y + a0.y * Wr[4*c+1].y + a0.z * Wr[4*c+2].y + a0.w * Wr[4*c+3].y;
        }
        acc.x += fmaxf(h0.x + p0.x, 0.f);
        acc.y += fmaxf(h0.y + p0.y, 0.f);
    }

    const float2 hd = *reinterpret_cast<const float2*>(hin + (size_t)dst * D_H + 2 * lane);
    acc.x += hd.x;
    acc.y += hd.y;
    return acc;
}

// ---------------------------------------------------------------------------
// Fused layer (0..2): hout = relu( z @ W_node + b_node ), z from edge_accum.
__global__ void __launch_bounds__(256, 4)
kaggr_mid(const float* __restrict__ hin, float* __restrict__ hout,
          const float* __restrict__ We, const float* __restrict__ be,
          const float* __restrict__ W_node, const float* __restrict__ b_node,
          int layer) {
    __shared__ float Ws[D_H * D_H];          // 16 KB
    __shared__ float bsh[D_H];
    __shared__ float z_sh[8][D_H];           // 8 warps/block

    const float* Wn = W_node + layer * D_H * D_H;
    for (int i = threadIdx.x; i < D_H * D_H / 4; i += blockDim.x)
        reinterpret_cast<float4*>(Ws)[i] = reinterpret_cast<const float4*>(Wn)[i];
    for (int i = threadIdx.x; i < D_H; i += blockDim.x)
        bsh[i] = (b_node + layer * D_H)[i];
    __syncthreads();

    const int lane = threadIdx.x & 31;
    const int w = threadIdx.x >> 5;
    const int dst = (blockIdx.x * blockDim.x + threadIdx.x) >> 5;
    if (dst >= N_NODES) return;

    const float* W = We + layer * E_DIM * D_H;
    float2 Wr[E_DIM];
    #pragma unroll
    for (int j = 0; j < E_DIM; j++)
        Wr[j] = *reinterpret_cast<const float2*>(W + j * D_H + 2 * lane);
    const float2 bias = *reinterpret_cast<const float2*>(be + layer * D_H + 2 * lane);

    const float2 z = edge_accum(hin, Wr, bias, dst, lane);

    // epilogue GEMV: out[2l..2l+1] = relu( b + sum_j z_j * Wn[j][2l..2l+1] )
    z_sh[w][2 * lane] = z.x;
    z_sh[w][2 * lane + 1] = z.y;
    __syncwarp();

    float acc0 = bsh[2 * lane];
    float acc1 = bsh[2 * lane + 1];
    const float2* Ws2 = reinterpret_cast<const float2*>(Ws);
    #pragma unroll 8
    for (int j = 0; j < D_H; j++) {
        const float zj = z_sh[w][j];
        const float2 wv = Ws2[j * 32 + lane];
        acc0 += zj * wv.x;
        acc1 += zj * wv.y;
    }
    float2 r;
    r.x = fmaxf(acc0, 0.f);
    r.y = fmaxf(acc1, 0.f);
    *reinterpret_cast<float2*>(hout + (size_t)dst * D_H + 2 * lane) = r;
}

// Fused last layer: g_s[dst] = z . W_out + b_out
__global__ void __launch_bounds__(256, 4)
kaggr_last(const float* __restrict__ hin,
           const float* __restrict__ We, const float* __restrict__ be,
           const float* __restrict__ W_out, const float* __restrict__ b_out) {
    const int lane = threadIdx.x & 31;
    const int dst = (blockIdx.x * blockDim.x + threadIdx.x) >> 5;
    if (dst >= N_NODES) return;

    const float* W = We + 3 * E_DIM * D_H;
    float2 Wr[E_DIM];
    #pragma unroll
    for (int j = 0; j < E_DIM; j++)
        Wr[j] = *reinterpret_cast<const float2*>(W + j * D_H + 2 * lane);
    const float2 bias = *reinterpret_cast<const float2*>(be + 3 * D_H + 2 * lane);

    const float2 z = edge_accum(hin, Wr, bias, dst, lane);

    const float2 wv = *reinterpret_cast<const float2*>(W_out + 2 * lane);
    float acc = z.x * wv.x + z.y * wv.y;
    #pragma unroll
    for (int o = 16; o > 0; o >>= 1)
        acc += __shfl_xor_sync(0xffffffffu, acc, o);
    if (lane == 0) g_s[dst] = acc + b_out[0];
}

// ---------------------------------------------------------------------------
// Mean pool: warp per graph; boundaries via binary search on sorted batch.
__global__ void kpool(const int* __restrict__ batch) {
    const int lane = threadIdx.x & 31;
    const int g = (blockIdx.x * blockDim.x + threadIdx.x) >> 5;
    if (g >= N_GRAPHS) return;

    // lower_bound(batch, g) and lower_bound(batch, g+1)
    int lo = 0, hi = N_NODES;
    while (lo < hi) { int m = (lo + hi) >> 1; if (batch[m] < g) lo = m + 1; else hi = m; }
    const int s0 = lo;
    hi = N_NODES;
    while (lo < hi) { int m = (lo + hi) >> 1; if (batch[m] < g + 1) lo = m + 1; else hi = m; }
    const int s1 = lo;

    float acc = 0.f;
    for (int i = s0 + lane; i < s1; i += 32) acc += g_s[i];
    #pragma unroll
    for (int o = 16; o > 0; o >>= 1)
        acc += __shfl_xor_sync(0xffffffffu, acc, o);
    if (lane == 0) g_pooled[g] = acc / fmaxf((float)(s1 - s0), 1.0f);
}

// batchnorm (training stats, biased var) -> sigmoid
__global__ void kfinal(const float* __restrict__ gamma,
                       const float* __restrict__ beta,
                       float* __restrict__ out) {
    __shared__ float sh[N_GRAPHS];
    const int t = threadIdx.x;
    const float p = g_pooled[t];

    sh[t] = p;
    __syncthreads();
    for (int s = N_GRAPHS / 2; s > 0; s >>= 1) {
        if (t < s) sh[t] += sh[t + s];
        __syncthreads();
    }
    const float m = sh[0] / (float)N_GRAPHS;
    __syncthreads();

    const float d = p - m;
    sh[t] = d * d;
    __syncthreads();
    for (int s = N_GRAPHS / 2; s > 0; s >>= 1) {
        if (t < s) sh[t] += sh[t + s];
        __syncthreads();
    }
    const float v = sh[0] / (float)N_GRAPHS;

    const float y = gamma[0] * d * rsqrtf(v + 1e-5f) + beta[0];
    out[t] = 1.0f / (1.0f + expf(-y));
}

// ---------------------------------------------------------------------------
extern "C" void kernel_launch(void* const* d_in, const int* in_sizes, int n_in,
                              void* d_out, int out_size) {
    const float* x    = (const float*)d_in[0];
    const int*   ei   = (const int*)d_in[1];     // int32 (JAX x64 disabled)
    const float* ea   = (const float*)d_in[2];
    const int*   bat  = (const int*)d_in[3];     // int32
    const float* Wh   = (const float*)d_in[4];
    const float* bh   = (const float*)d_in[5];
    const float* We   = (const float*)d_in[6];
    const float* be   = (const float*)d_in[7];
    const float* Wout = (const float*)d_in[8];
    const float* bout = (const float*)d_in[9];
    const float* gam  = (const float*)d_in[10];
    const float* bet  = (const float*)d_in[11];
    float* out = (float*)d_out;

    // --- CSR build + edge permutation ---
    kzero_cnt<<<64, 256>>>();
    kprep_edges<<<(N_EDGES + 255) / 256, 256>>>(ei);
    kscan1<<<N_SCAN_BLOCKS, SCAN_BS>>>();
    kscan2<<<1, SCAN_BS>>>();
    kscan3<<<(N_NODES + 255) / 256, 256>>>();
    kfillperm<<<(N_EDGES + 255) / 256, 256>>>(ei, (const float4*)ea);

    // --- 4 fused GINE layers (ping-pong; layer 0 reads x directly) ---
    const int aggr_blocks = (N_NODES * 32 + 255) / 256;   // warp per node
    float* hA; float* hB;
    // device-symbol pointers resolved at compile time inside kernels; here we
    // just pass them via the global symbols' addresses using unqualified refs.
    // (cudaGetSymbolAddress is host API & not graph-hostile, but avoid it:
    //  kernels take raw pointers; use helper launches below.)
    // We obtain the addresses via a tiny trick: kernels accept pointers, and
    // the globals are visible to device code; for host we use the fact that
    // CUDA allows taking &g_hA in device code only. So instead we launch with
    // nullptrs replaced by symbol-bound wrappers:
    // Simplest correct approach: dedicated wrapper kernels are overkill —
    // use cudaGetSymbolAddress once per launch (host API, allowed: it is not
    // an allocation and is graph-capture safe since it's not stream work).
    cudaGetSymbolAddress((void**)&hA, g_hA);
    cudaGetSymbolAddress((void**)&hB, g_hB);

    kaggr_mid<<<aggr_blocks, 256>>>(x,  hB, We, be, Wh, bh, 0);
    kaggr_mid<<<aggr_blocks, 256>>>(hB, hA, We, be, Wh, bh, 1);
    kaggr_mid<<<aggr_blocks, 256>>>(hA, hB, We, be, Wh, bh, 2);
    kaggr_last<<<aggr_blocks, 256>>>(hB, We, be, Wout, bout);

    kpool<<<(N_GRAPHS * 32 + 255) / 256, 256>>>(bat);
    kfinal<<<1, N_GRAPHS>>>(gam, bet, out);
}

// round 6
// speedup vs baseline: 1.2588x; 1.1060x over previous
#include <cuda_runtime.h>
#include <cstdint>

#define N_NODES  50000
#define N_EDGES  800000
#define N_GRAPHS 512
#define D_H      64
#define E_DIM    16
#define SCAN_BS  256
#define N_SCAN_BLOCKS ((N_NODES + SCAN_BS - 1) / SCAN_BS)   // 196

typedef unsigned long long ull;

// Blackwell packed f32x2 ops
#define PACK2DUP(d, a)   asm("mov.b64 %0, {%1, %1};" : "=l"(d) : "f"(a))
#define FMA2(d, a, b, c) asm("fma.rn.f32x2 %0, %1, %2, %3;" : "=l"(d) : "l"(a), "l"(b), "l"(c))
#define ADD2(d, a, b)    asm("add.rn.f32x2 %0, %1, %2;" : "=l"(d) : "l"(a), "l"(b))
#define UNPACK2(lo, hi, s) asm("mov.b64 {%0, %1}, %2;" : "=f"(lo), "=f"(hi) : "l"(s))

// ---------------------------------------------------------------------------
// Static scratch
__device__ __align__(16) float g_hA[N_NODES * D_H];
__device__ __align__(16) float g_hB[N_NODES * D_H];
__device__ __align__(16) float g_z[N_NODES * D_H];
__device__ __align__(16) float g_ea_perm[N_EDGES * E_DIM];   // dst-ordered edge_attr
__device__ int   g_src_perm[N_EDGES];                        // dst-ordered src
__device__ float g_s[N_NODES];
__device__ float g_pooled[N_GRAPHS];
__device__ int   g_cnt[N_NODES];
__device__ int   g_sloc[N_NODES];
__device__ int   g_bsum[N_SCAN_BLOCKS];
__device__ int   g_rowptr[N_NODES + 1];
__device__ int   g_cursor[N_NODES];

// ---------------------------------------------------------------------------
__global__ void kzero_cnt() {
    int t = blockIdx.x * blockDim.x + threadIdx.x;
    for (int i = t; i < N_NODES; i += gridDim.x * blockDim.x) g_cnt[i] = 0;
}

__global__ void kprep_edges(const int* __restrict__ ei) {
    int e = blockIdx.x * blockDim.x + threadIdx.x;
    if (e < N_EDGES) atomicAdd(&g_cnt[ei[N_EDGES + e]], 1);
}

__global__ void kscan1() {
    __shared__ int sh[SCAN_BS];
    const int t = threadIdx.x;
    const int i = blockIdx.x * SCAN_BS + t;
    int v = (i < N_NODES) ? g_cnt[i] : 0;
    sh[t] = v;
    __syncthreads();
    for (int off = 1; off < SCAN_BS; off <<= 1) {
        int add = (t >= off) ? sh[t - off] : 0;
        __syncthreads();
        sh[t] += add;
        __syncthreads();
    }
    if (i < N_NODES) g_sloc[i] = sh[t];
    if (t == SCAN_BS - 1) g_bsum[blockIdx.x] = sh[t];
}

__global__ void kscan2() {
    __shared__ int sh[SCAN_BS];
    const int t = threadIdx.x;
    int v = (t < N_SCAN_BLOCKS) ? g_bsum[t] : 0;
    sh[t] = v;
    __syncthreads();
    for (int off = 1; off < SCAN_BS; off <<= 1) {
        int add = (t >= off) ? sh[t - off] : 0;
        __syncthreads();
        sh[t] += add;
        __syncthreads();
    }
    if (t < N_SCAN_BLOCKS) g_bsum[t] = sh[t] - v;   // exclusive
}

__global__ void kscan3() {
    int i = blockIdx.x * blockDim.x + threadIdx.x;
    if (i < N_NODES) {
        int ex = g_sloc[i] - g_cnt[i] + g_bsum[i / SCAN_BS];
        g_rowptr[i] = ex;
        g_cursor[i] = ex;
        if (i == 0) g_rowptr[N_NODES] = N_EDGES;
    }
}

__global__ void kfillperm(const int* __restrict__ ei,
                          const float4* __restrict__ ea4) {
    int e = blockIdx.x * blockDim.x + threadIdx.x;
    if (e >= N_EDGES) return;
    int pos = atomicAdd(&g_cursor[ei[N_EDGES + e]], 1);
    g_src_perm[pos] = ei[e];
    float4* dst = reinterpret_cast<float4*>(g_ea_perm) + (size_t)pos * 4;
    const float4* src = ea4 + (size_t)e * 4;
    dst[0] = src[0];
    dst[1] = src[1];
    dst[2] = src[2];
    dst[3] = src[3];
}

// ---------------------------------------------------------------------------
// Edge accumulation core (f32x2): warp per dst node; lane owns ch (2l, 2l+1).
__device__ __forceinline__ float2 edge_accum(const float* __restrict__ hin,
                                             const ull* __restrict__ Wr2,  // [E_DIM]
                                             ull bias64, int dst, int lane) {
    const int kb = g_rowptr[dst];
    const int ke = g_rowptr[dst + 1];
    float accx = 0.f, accy = 0.f;
    ull zero64;
    { float z0 = 0.f; PACK2DUP(zero64, z0); }

    int k = kb;
    for (; k + 2 <= ke; k += 2) {
        const int s0 = g_src_perm[k];
        const int s1 = g_src_perm[k + 1];
        const ull h0 = *reinterpret_cast<const ull*>(hin + (size_t)s0 * D_H + 2 * lane);
        const ull h1 = *reinterpret_cast<const ull*>(hin + (size_t)s1 * D_H + 2 * lane);

        ull p0a = bias64, p0b = zero64, p1a = bias64, p1b = zero64;
        const float4* A = reinterpret_cast<const float4*>(g_ea_perm + (size_t)k * E_DIM);
        #pragma unroll
        for (int c = 0; c < 4; c++) {
            const float4 a0 = A[c];
            const float4 a1 = A[4 + c];
            ull d;
            PACK2DUP(d, a0.x); FMA2(p0a, d, Wr2[4*c+0], p0a);
            PACK2DUP(d, a0.y); FMA2(p0b, d, Wr2[4*c+1], p0b);
            PACK2DUP(d, a0.z); FMA2(p0a, d, Wr2[4*c+2], p0a);
            PACK2DUP(d, a0.w); FMA2(p0b, d, Wr2[4*c+3], p0b);
            PACK2DUP(d, a1.x); FMA2(p1a, d, Wr2[4*c+0], p1a);
            PACK2DUP(d, a1.y); FMA2(p1b, d, Wr2[4*c+1], p1b);
            PACK2DUP(d, a1.z); FMA2(p1a, d, Wr2[4*c+2], p1a);
            PACK2DUP(d, a1.w); FMA2(p1b, d, Wr2[4*c+3], p1b);
        }
        ull u0, u1;
        ADD2(u0, p0a, p0b); ADD2(u0, u0, h0);
        ADD2(u1, p1a, p1b); ADD2(u1, u1, h1);
        float x0, y0, x1, y1;
        UNPACK2(x0, y0, u0);
        UNPACK2(x1, y1, u1);
        accx += fmaxf(x0, 0.f) + fmaxf(x1, 0.f);
        accy += fmaxf(y0, 0.f) + fmaxf(y1, 0.f);
    }
    if (k < ke) {
        const int s0 = g_src_perm[k];
        const ull h0 = *reinterpret_cast<const ull*>(hin + (size_t)s0 * D_H + 2 * lane);
        ull p0a = bias64, p0b = zero64;
        const float4* A = reinterpret_cast<const float4*>(g_ea_perm + (size_t)k * E_DIM);
        #pragma unroll
        for (int c = 0; c < 4; c++) {
            const float4 a0 = A[c];
            ull d;
            PACK2DUP(d, a0.x); FMA2(p0a, d, Wr2[4*c+0], p0a);
            PACK2DUP(d, a0.y); FMA2(p0b, d, Wr2[4*c+1], p0b);
            PACK2DUP(d, a0.z); FMA2(p0a, d, Wr2[4*c+2], p0a);
            PACK2DUP(d, a0.w); FMA2(p0b, d, Wr2[4*c+3], p0b);
        }
        ull u0;
        ADD2(u0, p0a, p0b); ADD2(u0, u0, h0);
        float x0, y0;
        UNPACK2(x0, y0, u0);
        accx += fmaxf(x0, 0.f);
        accy += fmaxf(y0, 0.f);
    }

    const float2 hd = *reinterpret_cast<const float2*>(hin + (size_t)dst * D_H + 2 * lane);
    return make_float2(accx + hd.x, accy + hd.y);
}

// Layers 0..2 aggregation: writes z = h + aggr to g_z.
__global__ void __launch_bounds__(256, 3)
kaggr(const float* __restrict__ hin,
      const float* __restrict__ We, const float* __restrict__ be, int layer) {
    const int lane = threadIdx.x & 31;
    const int dst = (blockIdx.x * blockDim.x + threadIdx.x) >> 5;
    if (dst >= N_NODES) return;

    const float* W = We + layer * E_DIM * D_H;
    ull Wr2[E_DIM];
    #pragma unroll
    for (int j = 0; j < E_DIM; j++)
        Wr2[j] = *reinterpret_cast<const ull*>(W + j * D_H + 2 * lane);
    const ull bias64 = *reinterpret_cast<const ull*>(be + layer * D_H + 2 * lane);

    const float2 z = edge_accum(hin, Wr2, bias64, dst, lane);
    *reinterpret_cast<float2*>(g_z + (size_t)dst * D_H + 2 * lane) = z;
}

// Last layer: aggregation + dot W_out fused.
__global__ void __launch_bounds__(256, 3)
kaggr_last(const float* __restrict__ hin,
           const float* __restrict__ We, const float* __restrict__ be,
           const float* __restrict__ W_out, const float* __restrict__ b_out) {
    const int lane = threadIdx.x & 31;
    const int dst = (blockIdx.x * blockDim.x + threadIdx.x) >> 5;
    if (dst >= N_NODES) return;

    const float* W = We + 3 * E_DIM * D_H;
    ull Wr2[E_DIM];
    #pragma unroll
    for (int j = 0; j < E_DIM; j++)
        Wr2[j] = *reinterpret_cast<const ull*>(W + j * D_H + 2 * lane);
    const ull bias64 = *reinterpret_cast<const ull*>(be + 3 * D_H + 2 * lane);

    const float2 z = edge_accum(hin, Wr2, bias64, dst, lane);

    const float2 wv = *reinterpret_cast<const float2*>(W_out + 2 * lane);
    float acc = z.x * wv.x + z.y * wv.y;
    #pragma unroll
    for (int o = 16; o > 0; o >>= 1)
        acc += __shfl_xor_sync(0xffffffffu, acc, o);
    if (lane == 0) g_s[dst] = acc + b_out[0];
}

// ---------------------------------------------------------------------------
// Node MLP: hout = relu(z @ W + b). 8 warps/block, 8 nodes/warp (64/block).
// W row LDS amortized across 8 nodes; f32x2 accumulation.
#define NODES_PER_WARP 8
__global__ void __launch_bounds__(256, 4)
knode(float* __restrict__ hout,
      const float* __restrict__ W_hidden, const float* __restrict__ b_hidden,
      int layer) {
    __shared__ __align__(16) float Ws[D_H * D_H];        // 16 KB
    __shared__ __align__(16) float z_sh[8][NODES_PER_WARP][D_H];  // 16 KB

    const float* Wn = W_hidden + layer * D_H * D_H;
    for (int i = threadIdx.x; i < D_H * D_H / 4; i += blockDim.x)
        reinterpret_cast<float4*>(Ws)[i] = reinterpret_cast<const float4*>(Wn)[i];
    __syncthreads();

    const int lane = threadIdx.x & 31;
    const int w = threadIdx.x >> 5;
    const int nodeBase = (blockIdx.x * 8 + w) * NODES_PER_WARP;
    if (nodeBase >= N_NODES) return;

    // stage 8 z rows (coalesced 256B per row)
    #pragma unroll
    for (int n = 0; n < NODES_PER_WARP; n++) {
        int node = nodeBase + n;
        if (node < N_NODES) {
            *reinterpret_cast<float2*>(&z_sh[w][n][2 * lane]) =
                *reinterpret_cast<const float2*>(g_z + (size_t)node * D_H + 2 * lane);
        }
    }
    __syncwarp();

    const ull bias64 = *reinterpret_cast<const ull*>(b_hidden + layer * D_H + 2 * lane);
    ull acc[NODES_PER_WARP];
    #pragma unroll
    for (int n = 0; n < NODES_PER_WARP; n++) acc[n] = bias64;

    const ull* Ws2 = reinterpret_cast<const ull*>(Ws);
    #pragma unroll 4
    for (int j = 0; j < D_H; j++) {
        const ull wv = Ws2[j * 32 + lane];      // W[j][2l..2l+1]
        #pragma unroll
        for (int n = 0; n < NODES_PER_WARP; n++) {
            ull d;
            PACK2DUP(d, z_sh[w][n][j]);
            FMA2(acc[n], d, wv, acc[n]);
        }
    }

    #pragma unroll
    for (int n = 0; n < NODES_PER_WARP; n++) {
        int node = nodeBase + n;
        if (node < N_NODES) {
            float a0, a1;
            UNPACK2(a0, a1, acc[n]);
            float2 r;
            r.x = fmaxf(a0, 0.f);
            r.y = fmaxf(a1, 0.f);
            *reinterpret_cast<float2*>(hout + (size_t)node * D_H + 2 * lane) = r;
        }
    }
}

// ---------------------------------------------------------------------------
__global__ void kpool(const int* __restrict__ batch) {
    const int lane = threadIdx.x & 31;
    const int g = (blockIdx.x * blockDim.x + threadIdx.x) >> 5;
    if (g >= N_GRAPHS) return;

    int lo = 0, hi = N_NODES;
    while (lo < hi) { int m = (lo + hi) >> 1; if (batch[m] < g) lo = m + 1; else hi = m; }
    const int s0 = lo;
    hi = N_NODES;
    while (lo < hi) { int m = (lo + hi) >> 1; if (batch[m] < g + 1) lo = m + 1; else hi = m; }
    const int s1 = lo;

    float acc = 0.f;
    for (int i = s0 + lane; i < s1; i += 32) acc += g_s[i];
    #pragma unroll
    for (int o = 16; o > 0; o >>= 1)
        acc += __shfl_xor_sync(0xffffffffu, acc, o);
    if (lane == 0) g_pooled[g] = acc / fmaxf((float)(s1 - s0), 1.0f);
}

__global__ void kfinal(const float* __restrict__ gamma,
                       const float* __restrict__ beta,
                       float* __restrict__ out) {
    __shared__ float sh[N_GRAPHS];
    const int t = threadIdx.x;
    const float p = g_pooled[t];

    sh[t] = p;
    __syncthreads();
    for (int s = N_GRAPHS / 2; s > 0; s >>= 1) {
        if (t < s) sh[t] += sh[t + s];
        __syncthreads();
    }
    const float m = sh[0] / (float)N_GRAPHS;
    __syncthreads();

    const float d = p - m;
    sh[t] = d * d;
    __syncthreads();
    for (int s = N_GRAPHS / 2; s > 0; s >>= 1) {
        if (t < s) sh[t] += sh[t + s];
        __syncthreads();
    }
    const float v = sh[0] / (float)N_GRAPHS;

    const float y = gamma[0] * d * rsqrtf(v + 1e-5f) + beta[0];
    out[t] = 1.0f / (1.0f + expf(-y));
}

// ---------------------------------------------------------------------------
extern "C" void kernel_launch(void* const* d_in, const int* in_sizes, int n_in,
                              void* d_out, int out_size) {
    const float* x    = (const float*)d_in[0];
    const int*   ei   = (const int*)d_in[1];     // int32 (JAX x64 disabled)
    const float* ea   = (const float*)d_in[2];
    const int*   bat  = (const int*)d_in[3];     // int32
    const float* Wh   = (const float*)d_in[4];
    const float* bh   = (const float*)d_in[5];
    const float* We   = (const float*)d_in[6];
    const float* be   = (const float*)d_in[7];
    const float* Wout = (const float*)d_in[8];
    const float* bout = (const float*)d_in[9];
    const float* gam  = (const float*)d_in[10];
    const float* bet  = (const float*)d_in[11];
    float* out = (float*)d_out;

    // --- CSR build + edge permutation ---
    kzero_cnt<<<64, 256>>>();
    kprep_edges<<<(N_EDGES + 255) / 256, 256>>>(ei);
    kscan1<<<N_SCAN_BLOCKS, SCAN_BS>>>();
    kscan2<<<1, SCAN_BS>>>();
    kscan3<<<(N_NODES + 255) / 256, 256>>>();
    kfillperm<<<(N_EDGES + 255) / 256, 256>>>(ei, (const float4*)ea);

    float* hA; float* hB;
    cudaGetSymbolAddress((void**)&hA, g_hA);
    cudaGetSymbolAddress((void**)&hB, g_hB);

    const int aggr_blocks  = (N_NODES * 32 + 255) / 256;           // warp per node
    const int node_blocks  = (N_NODES + 63) / 64;                  // 64 nodes per block

    kaggr<<<aggr_blocks, 256>>>(x, We, be, 0);
    knode<<<node_blocks, 256>>>(hB, Wh, bh, 0);
    kaggr<<<aggr_blocks, 256>>>(hB, We, be, 1);
    knode<<<node_blocks, 256>>>(hA, Wh, bh, 1);
    kaggr<<<aggr_blocks, 256>>>(hA, We, be, 2);
    knode<<<node_blocks, 256>>>(hB, Wh, bh, 2);
    kaggr_last<<<aggr_blocks, 256>>>(hB, We, be, Wout, bout);

    kpool<<<(N_GRAPHS * 32 + 255) / 256, 256>>>(bat);
    kfinal<<<1, N_GRAPHS>>>(gam, bet, out);
}

// round 7
// speedup vs baseline: 1.6564x; 1.3159x over previous
#include <cuda_runtime.h>
#include <cstdint>

#define N_NODES  50000
#define N_EDGES  800000
#define N_GRAPHS 512
#define D_H      64
#define E_DIM    16
#define SCAN_BS  256
#define N_SCAN_BLOCKS ((N_NODES + SCAN_BS - 1) / SCAN_BS)   // 196
#define CAP      64   // edges staged per sweep per warp

typedef unsigned long long ull;

// Blackwell packed f32x2 ops. PACKAB of two different regs is pair-aliasable.
#define PACKAB(d, a, b)  asm("mov.b64 %0, {%1, %2};" : "=l"(d) : "f"(a), "f"(b))
#define FMA2(d, a, b, c) asm("fma.rn.f32x2 %0, %1, %2, %3;" : "=l"(d) : "l"(a), "l"(b), "l"(c))
#define MUL2(d, a, b)    asm("mul.rn.f32x2 %0, %1, %2;" : "=l"(d) : "l"(a), "l"(b))
#define UNPACK2(lo, hi, s) asm("mov.b64 {%0, %1}, %2;" : "=f"(lo), "=f"(hi) : "l"(s))

// ---------------------------------------------------------------------------
// Static scratch
__device__ __align__(16) float g_hA[N_NODES * D_H];
__device__ __align__(16) float g_hB[N_NODES * D_H];
__device__ __align__(16) float g_z[N_NODES * D_H];
__device__ __align__(16) float g_ea_perm[N_EDGES * E_DIM];   // dst-ordered edge_attr
__device__ int   g_src_perm[N_EDGES];                        // dst-ordered src
__device__ float g_s[N_NODES];
__device__ float g_pooled[N_GRAPHS];
__device__ int   g_cnt[N_NODES];
__device__ int   g_sloc[N_NODES];
__device__ int   g_bsum[N_SCAN_BLOCKS];
__device__ int   g_rowptr[N_NODES + 1];
__device__ int   g_cursor[N_NODES];

// ---------------------------------------------------------------------------
__global__ void kzero_cnt() {
    int t = blockIdx.x * blockDim.x + threadIdx.x;
    for (int i = t; i < N_NODES; i += gridDim.x * blockDim.x) g_cnt[i] = 0;
}

__global__ void kprep_edges(const int* __restrict__ ei) {
    int e = blockIdx.x * blockDim.x + threadIdx.x;
    if (e < N_EDGES) atomicAdd(&g_cnt[ei[N_EDGES + e]], 1);
}

__global__ void kscan1() {
    __shared__ int sh[SCAN_BS];
    const int t = threadIdx.x;
    const int i = blockIdx.x * SCAN_BS + t;
    int v = (i < N_NODES) ? g_cnt[i] : 0;
    sh[t] = v;
    __syncthreads();
    for (int off = 1; off < SCAN_BS; off <<= 1) {
        int add = (t >= off) ? sh[t - off] : 0;
        __syncthreads();
        sh[t] += add;
        __syncthreads();
    }
    if (i < N_NODES) g_sloc[i] = sh[t];
    if (t == SCAN_BS - 1) g_bsum[blockIdx.x] = sh[t];
}

__global__ void kscan2() {
    __shared__ int sh[SCAN_BS];
    const int t = threadIdx.x;
    int v = (t < N_SCAN_BLOCKS) ? g_bsum[t] : 0;
    sh[t] = v;
    __syncthreads();
    for (int off = 1; off < SCAN_BS; off <<= 1) {
        int add = (t >= off) ? sh[t - off] : 0;
        __syncthreads();
        sh[t] += add;
        __syncthreads();
    }
    if (t < N_SCAN_BLOCKS) g_bsum[t] = sh[t] - v;   // exclusive
}

__global__ void kscan3() {
    int i = blockIdx.x * blockDim.x + threadIdx.x;
    if (i < N_NODES) {
        int ex = g_sloc[i] - g_cnt[i] + g_bsum[i / SCAN_BS];
        g_rowptr[i] = ex;
        g_cursor[i] = ex;
        if (i == 0) g_rowptr[N_NODES] = N_EDGES;
    }
}

__global__ void kfillperm(const int* __restrict__ ei,
                          const float4* __restrict__ ea4) {
    int e = blockIdx.x * blockDim.x + threadIdx.x;
    if (e >= N_EDGES) return;
    int pos = atomicAdd(&g_cursor[ei[N_EDGES + e]], 1);
    g_src_perm[pos] = ei[e];
    float4* dst = reinterpret_cast<float4*>(g_ea_perm) + (size_t)pos * 4;
    const float4* src = ea4 + (size_t)e * 4;
    dst[0] = src[0];
    dst[1] = src[1];
    dst[2] = src[2];
    dst[3] = src[3];
}

// ---------------------------------------------------------------------------
// Edge projection for one edge (16 values in shared) -> (e[c0], e[c1]).
// j-pair vectorized: acc_c = sum_jp (a[2jp],a[2jp+1]) .* Wp_c[jp]; hsum at end.
__device__ __forceinline__ float2 proj16(const float4* __restrict__ A,
                                         const ull* Wp0, const ull* Wp1) {
    const float4 v0 = A[0], v1 = A[1], v2 = A[2], v3 = A[3];
    ull a0, a1, a2, a3, a4, a5, a6, a7;
    PACKAB(a0, v0.x, v0.y); PACKAB(a1, v0.z, v0.w);
    PACKAB(a2, v1.x, v1.y); PACKAB(a3, v1.z, v1.w);
    PACKAB(a4, v2.x, v2.y); PACKAB(a5, v2.z, v2.w);
    PACKAB(a6, v3.x, v3.y); PACKAB(a7, v3.z, v3.w);
    ull p0, p1;
    MUL2(p0, a0, Wp0[0]);     MUL2(p1, a0, Wp1[0]);
    FMA2(p0, a1, Wp0[1], p0); FMA2(p1, a1, Wp1[1], p1);
    FMA2(p0, a2, Wp0[2], p0); FMA2(p1, a2, Wp1[2], p1);
    FMA2(p0, a3, Wp0[3], p0); FMA2(p1, a3, Wp1[3], p1);
    FMA2(p0, a4, Wp0[4], p0); FMA2(p1, a4, Wp1[4], p1);
    FMA2(p0, a5, Wp0[5], p0); FMA2(p1, a5, Wp1[5], p1);
    FMA2(p0, a6, Wp0[6], p0); FMA2(p1, a6, Wp1[6], p1);
    FMA2(p0, a7, Wp0[7], p0); FMA2(p1, a7, Wp1[7], p1);
    float l0, h0, l1, h1;
    UNPACK2(l0, h0, p0);
    UNPACK2(l1, h1, p1);
    return make_float2(l0 + h0, l1 + h1);
}

// Warp-per-node edge accumulation with shared-staged ea/src.
__device__ __forceinline__ float2 edge_core(const float* __restrict__ hin,
                                            const ull* Wp0, const ull* Wp1,
                                            float b0, float b1,
                                            int dst, int lane,
                                            float4* sea, int* ssrc) {
    const int kb = g_rowptr[dst];
    const int ke = g_rowptr[dst + 1];
    const float2 hd = *reinterpret_cast<const float2*>(hin + (size_t)dst * D_H + 2 * lane);
    float accx = 0.f, accy = 0.f;

    for (int base = kb; base < ke; base += CAP) {
        const int nst = min(ke - base, CAP);
        // cooperative coalesced staging
        if (lane < nst)      ssrc[lane]      = g_src_perm[base + lane];
        if (lane + 32 < nst) ssrc[lane + 32] = g_src_perm[base + lane + 32];
        const float4* gsrc = reinterpret_cast<const float4*>(g_ea_perm) + (size_t)base * 4;
        for (int i = lane; i < nst * 4; i += 32) sea[i] = gsrc[i];
        __syncwarp();

        int k = 0;
        for (; k + 2 <= nst; k += 2) {
            const int s0 = ssrc[k], s1 = ssrc[k + 1];
            const float2 h0 = *reinterpret_cast<const float2*>(hin + (size_t)s0 * D_H + 2 * lane);
            const float2 h1 = *reinterpret_cast<const float2*>(hin + (size_t)s1 * D_H + 2 * lane);
            const float2 e0 = proj16(sea + (size_t)k * 4, Wp0, Wp1);
            const float2 e1 = proj16(sea + (size_t)(k + 1) * 4, Wp0, Wp1);
            accx += fmaxf(h0.x + e0.x + b0, 0.f) + fmaxf(h1.x + e1.x + b0, 0.f);
            accy += fmaxf(h0.y + e0.y + b1, 0.f) + fmaxf(h1.y + e1.y + b1, 0.f);
        }
        if (k < nst) {
            const int s0 = ssrc[k];
            const float2 h0 = *reinterpret_cast<const float2*>(hin + (size_t)s0 * D_H + 2 * lane);
            const float2 e0 = proj16(sea + (size_t)k * 4, Wp0, Wp1);
            accx += fmaxf(h0.x + e0.x + b0, 0.f);
            accy += fmaxf(h0.y + e0.y + b1, 0.f);
        }
        __syncwarp();
    }
    return make_float2(accx + hd.x, accy + hd.y);
}

// Layers 0..2 aggregation: writes z = h + aggr to g_z. 8 warps = 8 nodes/block.
__global__ void __launch_bounds__(256, 3)
kaggr(const float* __restrict__ hin,
      const float* __restrict__ We, const float* __restrict__ be, int layer) {
    __shared__ __align__(16) float4 sea_s[8][CAP * 4];   // 32 KB
    __shared__ int ssrc_s[8][CAP];                       // 2 KB
    const int lane = threadIdx.x & 31;
    const int w = threadIdx.x >> 5;
    const int dst = blockIdx.x * 8 + w;
    if (dst >= N_NODES) return;

    const float* W = We + layer * E_DIM * D_H;
    const int c0 = 2 * lane;
    ull Wp0[8], Wp1[8];
    #pragma unroll
    for (int jp = 0; jp < 8; jp++) {
        PACKAB(Wp0[jp], W[(2 * jp) * D_H + c0],     W[(2 * jp + 1) * D_H + c0]);
        PACKAB(Wp1[jp], W[(2 * jp) * D_H + c0 + 1], W[(2 * jp + 1) * D_H + c0 + 1]);
    }
    const float b0 = be[layer * D_H + c0];
    const float b1 = be[layer * D_H + c0 + 1];

    const float2 z = edge_core(hin, Wp0, Wp1, b0, b1, dst, lane, sea_s[w], ssrc_s[w]);
    *reinterpret_cast<float2*>(g_z + (size_t)dst * D_H + c0) = z;
}

// Last layer: aggregation + dot W_out fused.
__global__ void __launch_bounds__(256, 3)
kaggr_last(const float* __restrict__ hin,
           const float* __restrict__ We, const float* __restrict__ be,
           const float* __restrict__ W_out, const float* __restrict__ b_out) {
    __shared__ __align__(16) float4 sea_s[8][CAP * 4];
    __shared__ int ssrc_s[8][CAP];
    const int lane = threadIdx.x & 31;
    const int w = threadIdx.x >> 5;
    const int dst = blockIdx.x * 8 + w;
    if (dst >= N_NODES) return;

    const float* W = We + 3 * E_DIM * D_H;
    const int c0 = 2 * lane;
    ull Wp0[8], Wp1[8];
    #pragma unroll
    for (int jp = 0; jp < 8; jp++) {
        PACKAB(Wp0[jp], W[(2 * jp) * D_H + c0],     W[(2 * jp + 1) * D_H + c0]);
        PACKAB(Wp1[jp], W[(2 * jp) * D_H + c0 + 1], W[(2 * jp + 1) * D_H + c0 + 1]);
    }
    const float b0 = be[3 * D_H + c0];
    const float b1 = be[3 * D_H + c0 + 1];

    const float2 z = edge_core(hin, Wp0, Wp1, b0, b1, dst, lane, sea_s[w], ssrc_s[w]);

    const float2 wv = *reinterpret_cast<const float2*>(W_out + c0);
    float acc = z.x * wv.x + z.y * wv.y;
    #pragma unroll
    for (int o = 16; o > 0; o >>= 1)
        acc += __shfl_xor_sync(0xffffffffu, acc, o);
    if (lane == 0) g_s[dst] = acc + b_out[0];
}

// ---------------------------------------------------------------------------
// Node MLP: hout = relu(z @ W + b). j-pair vectorized, 4 nodes/warp.
#define NPW 4
__global__ void __launch_bounds__(256, 4)
knode(float* __restrict__ hout,
      const float* __restrict__ W_hidden, const float* __restrict__ b_hidden,
      int layer) {
    __shared__ __align__(16) ull Wp_sh[(D_H / 2) * D_H];   // 16 KB, [jp][c]
    __shared__ __align__(16) float z_sh[8][NPW][D_H];      // 8 KB

    const float* Wn = W_hidden + layer * D_H * D_H;
    for (int idx = threadIdx.x; idx < (D_H / 2) * D_H; idx += 256) {
        const int jp = idx >> 6, c = idx & 63;
        ull t;
        PACKAB(t, Wn[(2 * jp) * D_H + c], Wn[(2 * jp + 1) * D_H + c]);
        Wp_sh[idx] = t;
    }
    __syncthreads();

    const int lane = threadIdx.x & 31;
    const int w = threadIdx.x >> 5;
    const int c0 = 2 * lane;
    const int nodeBase = (blockIdx.x * 8 + w) * NPW;
    if (nodeBase >= N_NODES) return;

    #pragma unroll
    for (int n = 0; n < NPW; n++) {
        const int node = nodeBase + n;
        if (node < N_NODES)
            *reinterpret_cast<float2*>(&z_sh[w][n][c0]) =
                *reinterpret_cast<const float2*>(g_z + (size_t)node * D_H + c0);
    }
    __syncwarp();

    ull acc0[NPW], acc1[NPW];
    #pragma unroll
    for (int n = 0; n < NPW; n++) { acc0[n] = 0ull; acc1[n] = 0ull; }  // (0.f,0.f)

    #pragma unroll 8
    for (int jp = 0; jp < D_H / 2; jp++) {
        const ull wv0 = Wp_sh[jp * D_H + c0];
        const ull wv1 = Wp_sh[jp * D_H + c0 + 1];
        #pragma unroll
        for (int n = 0; n < NPW; n++) {
            const ull zp = *reinterpret_cast<const ull*>(&z_sh[w][n][2 * jp]);
            FMA2(acc0[n], zp, wv0, acc0[n]);
            FMA2(acc1[n], zp, wv1, acc1[n]);
        }
    }

    const float b0 = b_hidden[layer * D_H + c0];
    const float b1 = b_hidden[layer * D_H + c0 + 1];
    #pragma unroll
    for (int n = 0; n < NPW; n++) {
        const int node = nodeBase + n;
        if (node < N_NODES) {
            float lo, hi;
            UNPACK2(lo, hi, acc0[n]);
            const float r0 = fmaxf(lo + hi + b0, 0.f);
            UNPACK2(lo, hi, acc1[n]);
            const float r1 = fmaxf(lo + hi + b1, 0.f);
            *reinterpret_cast<float2*>(hout + (size_t)node * D_H + c0) = make_float2(r0, r1);
        }
    }
}

// ---------------------------------------------------------------------------
__global__ void kpool(const int* __restrict__ batch) {
    const int lane = threadIdx.x & 31;
    const int g = (blockIdx.x * blockDim.x + threadIdx.x) >> 5;
    if (g >= N_GRAPHS) return;

    int lo = 0, hi = N_NODES;
    while (lo < hi) { int m = (lo + hi) >> 1; if (batch[m] < g) lo = m + 1; else hi = m; }
    const int s0 = lo;
    hi = N_NODES;
    while (lo < hi) { int m = (lo + hi) >> 1; if (batch[m] < g + 1) lo = m + 1; else hi = m; }
    const int s1 = lo;

    float acc = 0.f;
    for (int i = s0 + lane; i < s1; i += 32) acc += g_s[i];
    #pragma unroll
    for (int o = 16; o > 0; o >>= 1)
        acc += __shfl_xor_sync(0xffffffffu, acc, o);
    if (lane == 0) g_pooled[g] = acc / fmaxf((float)(s1 - s0), 1.0f);
}

__global__ void kfinal(const float* __restrict__ gamma,
                       const float* __restrict__ beta,
                       float* __restrict__ out) {
    __shared__ float sh[N_GRAPHS];
    const int t = threadIdx.x;
    const float p = g_pooled[t];

    sh[t] = p;
    __syncthreads();
    for (int s = N_GRAPHS / 2; s > 0; s >>= 1) {
        if (t < s) sh[t] += sh[t + s];
        __syncthreads();
    }
    const float m = sh[0] / (float)N_GRAPHS;
    __syncthreads();

    const float d = p - m;
    sh[t] = d * d;
    __syncthreads();
    for (int s = N_GRAPHS / 2; s > 0; s >>= 1) {
        if (t < s) sh[t] += sh[t + s];
        __syncthreads();
    }
    const float v = sh[0] / (float)N_GRAPHS;

    const float y = gamma[0] * d * rsqrtf(v + 1e-5f) + beta[0];
    out[t] = 1.0f / (1.0f + expf(-y));
}

// ---------------------------------------------------------------------------
extern "C" void kernel_launch(void* const* d_in, const int* in_sizes, int n_in,
                              void* d_out, int out_size) {
    const float* x    = (const float*)d_in[0];
    const int*   ei   = (const int*)d_in[1];     // int32 (JAX x64 disabled)
    const float* ea   = (const float*)d_in[2];
    const int*   bat  = (const int*)d_in[3];     // int32
    const float* Wh   = (const float*)d_in[4];
    const float* bh   = (const float*)d_in[5];
    const float* We   = (const float*)d_in[6];
    const float* be   = (const float*)d_in[7];
    const float* Wout = (const float*)d_in[8];
    const float* bout = (const float*)d_in[9];
    const float* gam  = (const float*)d_in[10];
    const float* bet  = (const float*)d_in[11];
    float* out = (float*)d_out;

    // --- CSR build + edge permutation ---
    kzero_cnt<<<64, 256>>>();
    kprep_edges<<<(N_EDGES + 255) / 256, 256>>>(ei);
    kscan1<<<N_SCAN_BLOCKS, SCAN_BS>>>();
    kscan2<<<1, SCAN_BS>>>();
    kscan3<<<(N_NODES + 255) / 256, 256>>>();
    kfillperm<<<(N_EDGES + 255) / 256, 256>>>(ei, (const float4*)ea);

    float* hA; float* hB;
    cudaGetSymbolAddress((void**)&hA, g_hA);
    cudaGetSymbolAddress((void**)&hB, g_hB);

    const int aggr_blocks = (N_NODES + 7) / 8;          // 8 nodes (warps) per block
    const int node_blocks = (N_NODES + 8 * NPW - 1) / (8 * NPW);

    kaggr<<<aggr_blocks, 256>>>(x, We, be, 0);
    knode<<<node_blocks, 256>>>(hB, Wh, bh, 0);
    kaggr<<<aggr_blocks, 256>>>(hB, We, be, 1);
    knode<<<node_blocks, 256>>>(hA, Wh, bh, 1);
    kaggr<<<aggr_blocks, 256>>>(hA, We, be, 2);
    knode<<<node_blocks, 256>>>(hB, Wh, bh, 2);
    kaggr_last<<<aggr_blocks, 256>>>(hB, We, be, Wout, bout);

    kpool<<<(N_GRAPHS * 32 + 255) / 256, 256>>>(bat);
    kfinal<<<1, N_GRAPHS>>>(gam, bet, out);
}